// round 4
// baseline (speedup 1.0000x reference)
#include <cuda_runtime.h>
#include <math.h>

// Problem constants
#define BB   256           // batch
#define KIN  8             // in_units
#define CC   1152          // in_channels
#define JJ   10            // num_units
#define DD   16            // unit_size
#define JD   160           // JJ*DD
#define XKC  (KIN*CC)      // 9216

// kernB (GEMM1) tiling: fine K-split for 2 blocks/SM
#define CB1  8             // capsules per chunk
#define NCH1 (CC/CB1)      // 144 chunks
#define RB1  (CB1*KIN)     // 64 reduction rows per block
#define BT1  128           // batch tile
// kernD (GEMM2) tiling: batch-split for 2 blocks/SM
#define CB2  16
#define NCH2 (CC/CB2)      // 72
#define RB2  (CB2*KIN)     // 128 output rows
#define BT2  64            // batch rows reduced per block
#define XSTR 132           // padded minor stride (16B-aligned, conflict-free)

typedef unsigned long long ull;

// ---------------------------------------------------------------------------
// Scratch (device globals; runtime allocation forbidden)
// ---------------------------------------------------------------------------
__device__ alignas(16) float g_spart[NCH1 * BB * JD];  // split-K partials (23.6MB)
__device__ alignas(16) float g_v[BB * JD];             // v[b][jd]
__device__ alignas(16) float g_b[CC * JJ];             // routing logits

__device__ __forceinline__ ull pack2(float x) {
    ull r; asm("mov.b64 %0, {%1, %1};" : "=l"(r) : "f"(x)); return r;
}
__device__ __forceinline__ void fma2(ull& d, ull a, ull b) {
    asm("fma.rn.f32x2 %0, %1, %2, %0;" : "+l"(d) : "l"(a), "l"(b));
}

// ---------------------------------------------------------------------------
// Kernel B (fused softmax + GEMM1):
//   s_partial[chunk][b][jd] += x[b,k,c] * softmax(b_ij)[c,j] * W[c,j,d,k]
// grid = (144, 2), block = 512, smem 75KB -> 2 blocks/SM (32 warps)
// thread tile: 4b x 10jd
// ---------------------------------------------------------------------------
__global__ void __launch_bounds__(512, 2) kernB(const float* __restrict__ x,
                                                const float* __restrict__ W) {
    extern __shared__ float sm[];
    float* Xs = sm;                     // RB1 * XSTR   [r][b]
    float* Ps = sm + RB1 * XSTR;        // RB1 * JD     [r][jd]
    float* cs = Ps + RB1 * JD;          // CB1 * JJ = 80

    int c0 = blockIdx.x * CB1;
    int b0 = blockIdx.y * BT1;
    int tid = threadIdx.x;

    // per-capsule softmax over J (8 capsules x 10 units)
    if (tid < CB1 * JJ) {
        int cl = tid / JJ, j = tid - cl * JJ;
        const float* br = g_b + (size_t)(c0 + cl) * JJ;
        float bv[JJ], mx = -1e30f;
#pragma unroll
        for (int q = 0; q < JJ; q++) { bv[q] = br[q]; mx = fmaxf(mx, bv[q]); }
        float sum = 0.f;
#pragma unroll
        for (int q = 0; q < JJ; q++) { bv[q] = expf(bv[q] - mx); sum += bv[q]; }
        cs[tid] = bv[j] / sum;
    }

    // X tile transposed to [r][b] (conflict-free STS.128)
    for (int i = tid; i < RB1 * (BT1 / 4); i += 512) {
        int r = i & 63, bq = i >> 6;
        int k = r >> 3, cl = r & 7;
        const float* xp = x + (size_t)(b0 + bq * 4) * XKC + k * CC + c0 + cl;
        float4 v;
        v.x = xp[0]; v.y = xp[XKC]; v.z = xp[2 * XKC]; v.w = xp[3 * XKC];
        *reinterpret_cast<float4*>(Xs + r * XSTR + bq * 4) = v;
    }
    __syncthreads();   // cs ready before scaling W

    // P tile: Ps[k*8+cl][jd] = cs[cl][jd>>4] * W[c0+cl, jd, k]
    for (int i = tid; i < RB1 * JD / 4; i += 512) {
        int cl = i / 320, rem = i - cl * 320;
        int jd = rem >> 1, k4 = rem & 1;
        float sc = cs[cl * JJ + (jd >> 4)];
        float4 wv = *reinterpret_cast<const float4*>(
            W + (size_t)(c0 + cl) * 1280 + jd * 8 + k4 * 4);
        int kb = k4 * 4;
        Ps[((kb + 0) * 8 + cl) * JD + jd] = sc * wv.x;
        Ps[((kb + 1) * 8 + cl) * JD + jd] = sc * wv.y;
        Ps[((kb + 2) * 8 + cl) * JD + jd] = sc * wv.z;
        Ps[((kb + 3) * 8 + cl) * JD + jd] = sc * wv.w;
    }
    __syncthreads();

    int tx = tid & 15, ty = tid >> 4;
    ull acc[4][5];
#pragma unroll
    for (int a = 0; a < 4; a++)
#pragma unroll
        for (int e = 0; e < 5; e++) acc[a][e] = 0ULL;

    const float* xp = Xs + ty * 4;
    const ull*   pp = reinterpret_cast<const ull*>(Ps + tx * 10);
#pragma unroll 4
    for (int r = 0; r < RB1; r++) {
        float4 xv = *reinterpret_cast<const float4*>(xp); xp += XSTR;
        ull p[5];
#pragma unroll
        for (int e = 0; e < 5; e++) p[e] = pp[e];
        pp += JD / 2;
        ull xd[4] = {pack2(xv.x), pack2(xv.y), pack2(xv.z), pack2(xv.w)};
#pragma unroll
        for (int a = 0; a < 4; a++)
#pragma unroll
            for (int e = 0; e < 5; e++) fma2(acc[a][e], xd[a], p[e]);
    }

    // direct global store of the 4x10 fragment (STG.64)
    float* dst = g_spart + (size_t)blockIdx.x * (BB * JD)
               + (size_t)(b0 + ty * 4) * JD + tx * 10;
#pragma unroll
    for (int a = 0; a < 4; a++) {
        ull* o = reinterpret_cast<ull*>(dst + a * JD);
#pragma unroll
        for (int e = 0; e < 5; e++) o[e] = acc[a][e];
    }
}

// ---------------------------------------------------------------------------
// Kernel C: reduce 144 split-K partials + squash -> v ; final iter -> d_out
// grid = 80, block = 512; shfl reduction over 16 d-lanes
// ---------------------------------------------------------------------------
__global__ void __launch_bounds__(512) kernC(float* __restrict__ out) {
    int idx = blockIdx.x * 512 + threadIdx.x;   // b*160 + j*16 + d
    float s = 1e-5f;                            // ref adds 1e-5 BEFORE magnitudes
    const float* sp = g_spart + idx;
#pragma unroll 8
    for (int ch = 0; ch < NCH1; ch++)
        s += sp[(size_t)ch * (BB * JD)];

    float mag = s * s;
#pragma unroll
    for (int off = 8; off; off >>= 1)
        mag += __shfl_xor_sync(0xffffffffu, mag, off, 16);

    float v = s * (mag / ((1.f + mag) * sqrtf(mag)));
    g_v[idx] = v;
    if (out) out[idx] = v;                      // (B,J,D,1) same linearization
}

// ---------------------------------------------------------------------------
// Kernel D: GEMM2  G[(k,c),(j,d)] = sum_b x[b,k,c] v[b,j,d] (64-b slice),
// contract with W into agreement, atomically update b_ij.
// grid = (72, 4), block = 512, smem 82KB -> 2 blocks/SM
// thread tile: 4r x 10jd
// ---------------------------------------------------------------------------
__global__ void __launch_bounds__(512, 2) kernD(const float* __restrict__ x,
                                                const float* __restrict__ W) {
    extern __shared__ float sm[];
    float* Xs = sm;                     // BT2 * XSTR  [b][r]
    float* Vs = sm + BT2 * XSTR;        // BT2 * JD

    int c0 = blockIdx.x * CB2;
    int b0 = blockIdx.y * BT2;
    int tid = threadIdx.x;

    for (int i = tid; i < BT2 * JD / 4; i += 512)
        reinterpret_cast<float4*>(Vs)[i] =
            *reinterpret_cast<const float4*>(g_v + (size_t)b0 * JD + i * 4);

    for (int i = tid; i < BT2 * (RB2 / 4); i += 512) {
        int b = i >> 5, rq = i & 31;
        int k = rq >> 2, cl4 = (rq & 3) * 4;
        float4 xv = *reinterpret_cast<const float4*>(
            x + (size_t)(b0 + b) * XKC + k * CC + c0 + cl4);
        *reinterpret_cast<float4*>(Xs + b * XSTR + k * 16 + cl4) = xv;
    }
    __syncthreads();

    int tx = tid & 15, ty = tid >> 4;
    ull acc[4][5];
#pragma unroll
    for (int a = 0; a < 4; a++)
#pragma unroll
        for (int e = 0; e < 5; e++) acc[a][e] = 0ULL;

    const float* xp = Xs + ty * 4;
    const ull*   vp = reinterpret_cast<const ull*>(Vs + tx * 10);
#pragma unroll 4
    for (int b = 0; b < BT2; b++) {
        float4 xv = *reinterpret_cast<const float4*>(xp); xp += XSTR;
        ull v[5];
#pragma unroll
        for (int e = 0; e < 5; e++) v[e] = vp[e];
        vp += JD / 2;
        ull xd[4] = {pack2(xv.x), pack2(xv.y), pack2(xv.z), pack2(xv.w)};
#pragma unroll
        for (int a = 0; a < 4; a++)
#pragma unroll
            for (int e = 0; e < 5; e++) fma2(acc[a][e], xd[a], v[e]);
    }
    __syncthreads();

    // stage full G tile (128r x 160jd = 80KB) into reused smem
    float* Gs = sm;
#pragma unroll
    for (int a = 0; a < 4; a++) {
        ull* grow = reinterpret_cast<ull*>(Gs + (ty * 4 + a) * JD + tx * 10);
#pragma unroll
        for (int e = 0; e < 5; e++) grow[e] = acc[a][e];
    }
    __syncthreads();

    // agreement[c,j] = sum_{k,d} W[c,j,d,k] * G[(k*16+cl)][(j*16+d)]
    if (tid < CB2 * JJ) {
        int cl = tid / JJ, j = tid - cl * JJ;
        const float* wr = W + (size_t)(c0 + cl) * 1280 + j * 128;
        float ag = 0.f;
#pragma unroll
        for (int k = 0; k < KIN; k++)
#pragma unroll
            for (int d = 0; d < DD; d++)
                ag = fmaf(wr[d * 8 + k], Gs[(k * 16 + cl) * JD + j * 16 + d], ag);
        atomicAdd(&g_b[(c0 + cl) * JJ + j], ag);
    }
}

// ---------------------------------------------------------------------------
// Host launcher (graph-capturable)
// ---------------------------------------------------------------------------
extern "C" void kernel_launch(void* const* d_in, const int* in_sizes, int n_in,
                              void* d_out, int out_size) {
    const float* x = (const float*)d_in[0];
    const float* W = (const float*)d_in[1];
    if (in_sizes[0] != BB * KIN * CC) {   // defensive mapping by element count
        x = (const float*)d_in[1];
        W = (const float*)d_in[0];
    }

    const int SMEM_B = (RB1 * XSTR + RB1 * JD + CB1 * JJ) * 4;  // 75072
    const int SMEM_D = (RB2 * JD) * 4;                          // 81920 (>= load layout)
    cudaFuncSetAttribute(kernB, cudaFuncAttributeMaxDynamicSharedMemorySize, SMEM_B);
    cudaFuncSetAttribute(kernD, cudaFuncAttributeMaxDynamicSharedMemorySize, SMEM_D);

    void* pb = nullptr;
    cudaGetSymbolAddress(&pb, g_b);
    cudaMemsetAsync(pb, 0, CC * JJ * sizeof(float));            // b_ij = 0 each call

    dim3 gB(NCH1, BB / BT1);   // (144, 2)
    dim3 gD(NCH2, BB / BT2);   // (72, 4)
    for (int it = 0; it < 4; it++) {
        kernB<<<gB, 512, SMEM_B>>>(x, W);                       // softmax+P+GEMM1
        kernC<<<(BB * JD) / 512, 512>>>(it == 3 ? (float*)d_out : nullptr);
        if (it < 3)                                             // iter-4 agreement dead
            kernD<<<gD, 512, SMEM_D>>>(x, W);                   // GEMM2 + agreement
    }
}